// round 15
// baseline (speedup 1.0000x reference)
#include <cuda_runtime.h>
#include <cuda_fp16.h>
#include <math.h>

#define B 64
#define S 512
#define H 512
#define IN 84
#define NC 100
#define XW 266

#define NGRP 8
#define GCTA 16
#define BPG 8
#define UPC 32
#define NCTA 128
#define NTH 256

// padded strides (halves): row stride ≡ 16 B mod 128 -> conflict-free ldmatrix
#define WST 648
#define XHST 520
#define XFST 136

#define XHBYTES (8 * XHST * 2)      // 8320
#define XFBUF   (8 * XFST * 2)      // 2176

// ---- static device scratch ----
__device__ unsigned short g_hx[2 * NGRP * 8 * XHST];             // [par][grp][8b][520] fp16
__device__ unsigned short g_fx[(size_t)S * NGRP * 8 * XFST];     // [s][grp][8b][136] fp16
__device__ float g_lstm[(size_t)S * H * B];                      // [S][H][B]
__device__ float g_sc[S * B];
__device__ float g_ctx[H * B];
__device__ unsigned g_ctrs[64];                                  // grp uses [grp*8]

// ---- SMEM layout (bytes) ----
#define OFF_W     0                     // 128 x 648 fp16 = 165888
#define OFF_XH    165888                // 8 x 520 fp16 = 8320
#define OFF_XF    174208                // 2 bufs x 8 x 136 fp16 = 4352
#define OFF_GSH   178560                // 128 x 9 f32 = 4608
#define OFF_MB    183168                // 3 mbars
#define SMEM_BYTES 183200

// ---- helpers ----
__device__ __forceinline__ unsigned smem_u32(const void* p) {
    return (unsigned)__cvta_generic_to_shared(p);
}
__device__ __forceinline__ void mbar_init(unsigned a, unsigned cnt) {
    asm volatile("mbarrier.init.shared.b64 [%0], %1;" :: "r"(a), "r"(cnt) : "memory");
}
__device__ __forceinline__ void mbar_expect(unsigned a, unsigned bytes) {
    asm volatile("mbarrier.arrive.expect_tx.shared.b64 _, [%0], %1;"
                 :: "r"(a), "r"(bytes) : "memory");
}
__device__ __forceinline__ void bulk_g2s(unsigned dst, const void* src,
                                         unsigned bytes, unsigned mbar) {
    asm volatile(
        "cp.async.bulk.shared::cluster.global.mbarrier::complete_tx::bytes "
        "[%0], [%1], %2, [%3];"
        :: "r"(dst), "l"(src), "r"(bytes), "r"(mbar) : "memory");
}
__device__ __forceinline__ void mbar_wait(unsigned a, unsigned parity) {
    asm volatile(
        "{\n\t.reg .pred P;\n\t"
        "W%=:\n\t"
        "mbarrier.try_wait.parity.shared.b64 P, [%0], %1, 0x989680;\n\t"
        "@P bra D%=;\n\t"
        "bra W%=;\n\t"
        "D%=:\n\t}"
        :: "r"(a), "r"(parity) : "memory");
}

#define LDSM4(r, addr) \
    asm volatile("ldmatrix.sync.aligned.m8n8.x4.shared.b16 {%0,%1,%2,%3}, [%4];" \
        : "=r"((r)[0]), "=r"((r)[1]), "=r"((r)[2]), "=r"((r)[3]) : "r"(addr))
#define LDSM2(r, addr) \
    asm volatile("ldmatrix.sync.aligned.m8n8.x2.shared.b16 {%0,%1}, [%2];" \
        : "=r"((r)[0]), "=r"((r)[1]) : "r"(addr))
#define MMAH16816(c, a, b0v, b1v) \
    asm volatile("mma.sync.aligned.m16n8k16.row.col.f32.f16.f16.f32 " \
        "{%0,%1,%2,%3}, {%4,%5,%6,%7}, {%8,%9}, {%0,%1,%2,%3};" \
        : "+f"((c)[0]), "+f"((c)[1]), "+f"((c)[2]), "+f"((c)[3]) \
        : "r"((a)[0]), "r"((a)[1]), "r"((a)[2]), "r"((a)[3]), "r"(b0v), "r"(b1v))

// one k-step (N=8): A x4 fragment + B x2 fragment -> 1 MMA
#define KSTEP1(aHI, bADDR) do {                           \
    unsigned ah[4], bh[2];                                \
    LDSM4(ah, aHI); LDSM2(bh, bADDR);                     \
    MMAH16816(cn0, ah, bh[0], bh[1]);                     \
} while (0)
#define KSTEPF(aHI, bADDR) do {                           \
    unsigned ah[4], bh[2];                                \
    LDSM4(ah, aHI); LDSM2(bh, bADDR);                     \
    MMAH16816(fcn0, ah, bh[0], bh[1]);                    \
} while (0)

__device__ __forceinline__ float sigf(float x) {
    return __fdividef(1.0f, 1.0f + __expf(-x));
}
__device__ __forceinline__ float tanhfast(float x) {
    return __fdividef(2.0f, 1.0f + __expf(-2.0f * x)) - 1.0f;
}
__device__ __forceinline__ unsigned short f16r(float v) {
    __half h = __float2half_rn(v);
    unsigned short r; memcpy(&r, &h, 2); return r;
}

// ============================================================ reset
__global__ void reset_kernel() {
    int t = blockIdx.x * blockDim.x + threadIdx.x;
    if (t < 64) g_ctrs[t] = 0u;
    if (t < (int)(sizeof(g_hx) / 4)) ((unsigned*)g_hx)[t] = 0u;
}

// ============================================================ preprocessing
__global__ void prep_kernel(const float* __restrict__ x) {
    int s = blockIdx.x;
    int b = threadIdx.x;                 // 64 threads
    int grp = b >> 3, bl = b & 7;
    unsigned short* fh = g_fx + (((size_t)s * NGRP + grp) * 8 + bl) * XFST;
    #pragma unroll 4
    for (int c = 0; c < XFST; c++) fh[c] = 0;

    const float* xp = x + ((size_t)b * S + s) * XW;
    float cx = xp[0], cy = xp[1];
    #pragma unroll
    for (int hnd = 0; hnd < 2; hnd++) {
        int pbase = (hnd == 0) ? 91 : 112;
        float mnx = 1e30f, mxx = -1e30f, mny = 1e30f, mxy = -1e30f;
        #pragma unroll
        for (int p = 0; p < 21; p++) {
            float px = xp[(pbase + p) * 2];
            float py = xp[(pbase + p) * 2 + 1];
            mnx = fminf(mnx, px); mxx = fmaxf(mxx, px);
            mny = fminf(mny, py); mxy = fmaxf(mxy, py);
        }
        float whx = mxx - mnx, why = mxy - mny;
        bool ok = (whx != 0.0f) && (why != 0.0f);
        float sx = ok ? whx : 1.0f;
        float sy = ok ? why : 1.0f;
        #pragma unroll
        for (int p = 0; p < 21; p++) {
            float px = (xp[(pbase + p) * 2] - cx) / sx;
            float py = (xp[(pbase + p) * 2 + 1] - cy) / sy;
            int i0 = hnd * 42 + p * 2;
            fh[i0]     = f16r(px);
            fh[i0 + 1] = f16r(py);
        }
    }
    fh[84] = f16r(1.0f);   // bias row
}

// ============================================================ recurrence
// CTA: grp = blk>>4 (8 batches), cg = blk&15 (32 units -> 128 gate rows)
// 8 warps x 16 M-rows, full K per warp; N=8.
__global__ void __launch_bounds__(NTH, 1)
lstm_kernel(const float* __restrict__ W_ih, const float* __restrict__ W_hh,
            const float* __restrict__ b_ih, const float* __restrict__ b_hh) {
    extern __shared__ char smc[];
    const int t = threadIdx.x;
    const int blk = blockIdx.x;
    const int grp = blk >> 4;
    const int cg = blk & 15;
    const int lane = t & 31;
    const int wid = t >> 5;
    const unsigned sbase = smem_u32(smc);

    // ---- one-time W staging: fp16 [128 rows][648 cols] (cols < 608 live) ----
    for (int idx = t; idx < 128 * 608; idx += NTH) {
        int r = idx & 127, k = idx >> 7;
        int grow = (r >> 5) * H + cg * UPC + (r & 31);
        float w;
        if (k < 512)        w = W_hh[(size_t)grow * H + k];
        else if (k < 596)   w = W_ih[(size_t)grow * IN + (k - 512)];
        else if (k == 596)  w = b_ih[grow] + b_hh[grow];
        else                w = 0.0f;
        ((__half*)(smc + OFF_W))[r * WST + k] = __float2half_rn(w);
    }
    if (t == 0) {
        mbar_init(sbase + OFF_MB + 0, 1);    // h
        mbar_init(sbase + OFF_MB + 8, 1);    // feats buf0
        mbar_init(sbase + OFF_MB + 16, 1);   // feats buf1
    }
    __syncthreads();

    const unsigned mbh = sbase + OFF_MB;
    const unsigned mbf = sbase + OFF_MB + 8;

    // ldmatrix per-lane addresses
    // A (row-major 16x16 tiles): lanes 0-15 rows @k, lanes 16-31 rows @k+8
    const unsigned aA = (unsigned)((wid * 16 + (lane & 15)) * WST + (lane >> 4) * 8) * 2;
    const unsigned aAhi = sbase + OFF_W + aA;
    // B x2 from [n][k]: lanes 0-7 -> (n, k+0); lanes 8-15 -> (n, k+8)
    const unsigned nrow = lane & 7;
    const unsigned kofs = ((lane >> 3) & 1) * 8;
    const unsigned aBh = sbase + OFF_XH + (unsigned)(nrow * XHST + kofs) * 2;
    const unsigned aBf = (unsigned)(nrow * XFST + kofs) * 2;

    // gate mapping: thread = (unit ul 0..31, batch gb 0..7)
    const int ul = t >> 3, gb = t & 7;
    const int u_glob = cg * UPC + ul;
    float creg = 0.0f;

    float* gsh = (float*)(smc + OFF_GSH);     // [128][9]
    unsigned* my_ctr = &g_ctrs[grp * 8];
    const unsigned short* hsrc_base = g_hx + (size_t)grp * 8 * XHST;
    const unsigned short* fsrc_base = g_fx + (size_t)grp * 8 * XFST;

    // ---- preloop: issue h(0) + feats(0); feats MMA for s=0 ----
    if (t == 0) {
        asm volatile("fence.proxy.async;" ::: "memory");
        mbar_expect(mbh, XHBYTES);
        bulk_g2s(sbase + OFF_XH, hsrc_base, XHBYTES, mbh);
        mbar_expect(mbf, XFBUF);
        bulk_g2s(sbase + OFF_XF, fsrc_base, XFBUF, mbf);
    }

    float fcn0[4] = {0, 0, 0, 0};
    mbar_wait(mbf, 0);
    #pragma unroll
    for (int j = 0; j < 6; j++)
        KSTEPF(aAhi + 1024 + j * 32, sbase + OFF_XF + aBf + j * 32);

    for (int s = 0; s < S; s++) {
        const int nxt = (s & 1) ^ 1;
        const unsigned par = (unsigned)(s & 1);

        // ---- t0: prefetch feats(s+1) ----
        if (t == 0 && s + 1 < S) {
            int nb = (s + 1) & 1;
            mbar_expect(mbf + nb * 8, XFBUF);
            bulk_g2s(sbase + OFF_XF + (unsigned)nb * XFBUF,
                     fsrc_base + (size_t)(s + 1) * NGRP * 8 * XFST,
                     XFBUF, mbf + nb * 8);
        }

        {
            float cn0[4] = {fcn0[0], fcn0[1], fcn0[2], fcn0[3]};

            // ---- h k-steps (32; W cols 0..511) ----
            mbar_wait(mbh, par);
            #pragma unroll 4
            for (int j = 0; j < 32; j++)
                KSTEP1(aAhi + j * 32, aBh + j * 32);

            // ---- D writeback to gsh[128][9] ----
            int r0 = wid * 16 + (lane >> 2);
            int c0 = (lane & 3) * 2;
            gsh[r0 * 9 + c0]           = cn0[0];
            gsh[r0 * 9 + c0 + 1]       = cn0[1];
            gsh[(r0 + 8) * 9 + c0]     = cn0[2];
            gsh[(r0 + 8) * 9 + c0 + 1] = cn0[3];
        }
        __syncthreads();

        // ---- gates: direct h + lstm stores ----
        {
            float gi = gsh[(0 * 32 + ul) * 9 + gb];
            float gf = gsh[(1 * 32 + ul) * 9 + gb];
            float gg = gsh[(2 * 32 + ul) * 9 + gb];
            float go = gsh[(3 * 32 + ul) * 9 + gb];
            float i_ = sigf(gi), f_ = sigf(gf);
            float g_ = tanhfast(gg), o_ = sigf(go);
            creg = f_ * creg + i_ * g_;
            float hn = o_ * tanhfast(creg);
            size_t hbase = (size_t)(nxt * NGRP + grp) * 8 * XHST;
            g_hx[hbase + gb * XHST + u_glob] = f16r(hn);
            g_lstm[((size_t)s * H + u_glob) * B + grp * BPG + gb] = hn;
        }
        __syncthreads();   // order gate stores before t0's release-arrive

        // ---- tail: arrive; feats MMA for s+1 under barrier drain; poll; issue h(s+1) ----
        if (s != S - 1) {
            if (t == 0) {
                asm volatile("red.add.release.gpu.u32 [%0], %1;"
                             :: "l"(my_ctr), "r"(1u) : "memory");
            }
            {
                const int fb2 = (s + 1) & 1;
                const unsigned fpar2 = (unsigned)(((s + 1) >> 1) & 1);
                mbar_wait(mbf + fb2 * 8, fpar2);
                fcn0[0] = fcn0[1] = fcn0[2] = fcn0[3] = 0.0f;
                const unsigned fba = sbase + OFF_XF + (unsigned)fb2 * XFBUF + aBf;
                #pragma unroll
                for (int j = 0; j < 6; j++)
                    KSTEPF(aAhi + 1024 + j * 32, fba + j * 32);
            }
            if (t == 0) {
                unsigned target = (unsigned)(s + 1) * GCTA;
                unsigned v;
                do {
                    asm volatile("ld.acquire.gpu.u32 %0, [%1];"
                                 : "=r"(v) : "l"(my_ctr) : "memory");
                } while (v < target);
                // h for s+1 is now globally visible -> issue TMA immediately
                asm volatile("fence.proxy.async;" ::: "memory");
                mbar_expect(mbh, XHBYTES);
                bulk_g2s(sbase + OFF_XH,
                         hsrc_base + (size_t)(nxt * NGRP) * 8 * XHST,
                         XHBYTES, mbh);
            }
            __syncthreads();
        }
    }
}

// ============================================================ attention
__global__ void __launch_bounds__(256)
scores_kernel(const float* __restrict__ attn_w) {
    __shared__ float aw[H];
    __shared__ float part[4 * 64];
    int t = threadIdx.x, s = blockIdx.x;
    int st = t >> 6, b = t & 63;
    for (int i = t; i < H; i += 256) aw[i] = attn_w[i];
    __syncthreads();
    const float* Ls = g_lstm + (size_t)s * H * B;
    float acc = 0.0f;
    #pragma unroll 8
    for (int h = st * 128; h < st * 128 + 128; h++)
        acc = fmaf(aw[h], Ls[h * B + b], acc);
    part[st * 64 + b] = acc;
    __syncthreads();
    if (st == 0)
        g_sc[s * B + b] = part[b] + part[64 + b] + part[128 + b] + part[192 + b];
}

__global__ void __launch_bounds__(256)
softmax_kernel(float* __restrict__ out) {
    __shared__ float s_red[8];
    int b = blockIdx.x, t = threadIdx.x;
    int lane = t & 31, warp = t >> 5;
    float v[2];
    v[0] = g_sc[t * B + b];
    v[1] = g_sc[(t + 256) * B + b];
    float m = fmaxf(v[0], v[1]);
    #pragma unroll
    for (int o = 16; o; o >>= 1) m = fmaxf(m, __shfl_xor_sync(~0u, m, o));
    if (lane == 0) s_red[warp] = m;
    __syncthreads();
    m = s_red[0];
    #pragma unroll
    for (int i = 1; i < 8; i++) m = fmaxf(m, s_red[i]);
    __syncthreads();
    float e0 = expf(v[0] - m), e1 = expf(v[1] - m);
    float sum = e0 + e1;
    #pragma unroll
    for (int o = 16; o; o >>= 1) sum += __shfl_xor_sync(~0u, sum, o);
    if (lane == 0) s_red[warp] = sum;
    __syncthreads();
    float tot = 0.0f;
    #pragma unroll
    for (int i = 0; i < 8; i++) tot += s_red[i];
    float inv = 1.0f / tot;
    float w0 = e0 * inv, w1 = e1 * inv;
    g_sc[t * B + b] = w0;
    g_sc[(t + 256) * B + b] = w1;
    out[NC * B + b * S + t] = w0;
    out[NC * B + b * S + t + 256] = w1;
}

__global__ void __launch_bounds__(256)
ctx_kernel() {
    __shared__ float part[4 * 64];
    int t = threadIdx.x, h = blockIdx.x;
    int st = t >> 6, b = t & 63;
    float acc = 0.0f;
    const float* Lb = g_lstm + (size_t)h * B + b;
    #pragma unroll 8
    for (int s = st * 128; s < st * 128 + 128; s++)
        acc = fmaf(g_sc[s * B + b], Lb[(size_t)s * H * B], acc);
    part[st * 64 + b] = acc;
    __syncthreads();
    if (st == 0)
        g_ctx[h * B + b] = part[b] + part[64 + b] + part[128 + b] + part[192 + b];
}

__global__ void __launch_bounds__(64)
fc_kernel(const float* __restrict__ fc_w, const float* __restrict__ fc_b,
          float* __restrict__ out) {
    __shared__ float wrow[H];
    int c = blockIdx.x, b = threadIdx.x;
    for (int i = b; i < H; i += 64) wrow[i] = fc_w[(size_t)c * H + i];
    __syncthreads();
    float acc = fc_b[c];
    #pragma unroll 8
    for (int h = 0; h < H; h++)
        acc = fmaf(wrow[h], g_ctx[h * B + b], acc);
    out[b * NC + c] = acc;
}

// ============================================================ launch
extern "C" void kernel_launch(void* const* d_in, const int* in_sizes, int n_in,
                              void* d_out, int out_size) {
    const float* x      = (const float*)d_in[0];
    const float* W_ih   = (const float*)d_in[1];
    const float* W_hh   = (const float*)d_in[2];
    const float* b_ih   = (const float*)d_in[3];
    const float* b_hh   = (const float*)d_in[4];
    const float* attn_w = (const float*)d_in[5];
    const float* fc_w   = (const float*)d_in[6];
    const float* fc_b   = (const float*)d_in[7];
    float* out = (float*)d_out;

    cudaFuncSetAttribute(lstm_kernel,
                         cudaFuncAttributeMaxDynamicSharedMemorySize, SMEM_BYTES);

    reset_kernel<<<260, 256>>>();
    prep_kernel<<<S, 64>>>(x);
    lstm_kernel<<<NCTA, NTH, SMEM_BYTES>>>(W_ih, W_hh, b_ih, b_hh);
    scores_kernel<<<S, 256>>>(attn_w);
    softmax_kernel<<<B, 256>>>(out);
    ctx_kernel<<<H, 256>>>();
    fc_kernel<<<NC, 64>>>(fc_w, fc_b, out);
}